// round 9
// baseline (speedup 1.0000x reference)
#include <cuda_runtime.h>
#include <cstdint>

#define SEQ     256
#define BATCH   512
#define IN_DIM  256
#define HDIM    8
#define DIN     264          // IN_DIM + HDIM
#define NROWS   (SEQ * BATCH)

// Scratch: pre-activations, bias folded in.
// Layout: zx[(t*BATCH + b)*32 + q*4 + g]  (gate-minor: recur lane does 1 LDG.128)
// Padded one t-row so the recur prefetch never reads OOB.
__device__ __align__(16) float g_zx[(size_t)(NROWS + BATCH) * 32];

// Ready flags: one per gemm tile (64 rows). fidx = t*8 + oct, oct = b>>6.
// [0,2048) = real flags, [2048,2304) = pad preset to 1 (t >= SEQ).
#define NFLAG_REAL 2048
#define NFLAG_PAD  2304
__device__ unsigned g_flag[NFLAG_PAD];

typedef unsigned long long ull;
#define ONE2 0x3F8000003F800000ULL

__device__ __forceinline__ void ffma2(ull &d, ull a, ull b) {
    asm("fma.rn.f32x2 %0, %1, %2, %0;" : "+l"(d) : "l"(a), "l"(b));
}
__device__ __forceinline__ ull mul2(ull a, ull b) {
    ull r; asm("mul.rn.f32x2 %0, %1, %2;" : "=l"(r) : "l"(a), "l"(b)); return r;
}
__device__ __forceinline__ ull pack2(float lo, float hi) {
    ull r; asm("mov.b64 %0, {%1, %2};" : "=l"(r) : "f"(lo), "f"(hi)); return r;
}
__device__ __forceinline__ void unpack2(float &lo, float &hi, ull v) {
    asm("mov.b64 {%0, %1}, %2;" : "=f"(lo), "=f"(hi) : "l"(v));
}
__device__ __forceinline__ float tanh_approx(float x) {
    float y; asm("tanh.approx.f32 %0, %1;" : "=f"(y) : "f"(x)); return y;
}
__device__ __forceinline__ void cpasync16(void* dst, const void* src) {
    unsigned ds = (unsigned)__cvta_generic_to_shared(dst);
    asm volatile("cp.async.cg.shared.global [%0], [%1], 16;" :: "r"(ds), "l"(src));
}
__device__ __forceinline__ void cp_commit() { asm volatile("cp.async.commit_group;"); }
template <int N> __device__ __forceinline__ void cp_wait() {
    asm volatile("cp.async.wait_group %0;" :: "n"(N));
}
__device__ __forceinline__ unsigned ld_acq(const unsigned* p) {
    unsigned v; asm volatile("ld.acquire.gpu.global.b32 %0, [%1];" : "=r"(v) : "l"(p)); return v;
}
__device__ __forceinline__ unsigned ld_rlx(const unsigned* p) {
    unsigned v; asm volatile("ld.relaxed.gpu.global.b32 %0, [%1];" : "=r"(v) : "l"(p)); return v;
}
__device__ __forceinline__ void st_rel(unsigned* p, unsigned v) {
    asm volatile("st.release.gpu.global.b32 [%0], %1;" :: "l"(p), "r"(v));
}
__device__ __forceinline__ void fence_acq() {
    asm volatile("fence.acq_rel.gpu;" ::: "memory");
}

__global__ void init_flags() {
    int i = blockIdx.x * blockDim.x + threadIdx.x;
    if (i < NFLAG_PAD) g_flag[i] = (i < NFLAG_REAL) ? 0u : 1u;
}

// ---------------------------------------------------------------------------
// Fused kernel. Blocks 0..15: recur (8 warps x 4 elements = 32 elements each).
// Blocks 16..2063: gemm tiles of 64 rows, st.release flag on completion.
// ---------------------------------------------------------------------------
#define GEMM_BLOCKS 2048
#define RECUR_BLOCKS 16
#define KCH    32
#define NCHUNK 8

struct RecurEx {                 // per-warp exchange strip (padded strides)
    float cv[4][36];             // cos float4 per (elem, qubit); stride 36 fl
    float h[4][12];              // h per (elem, qubit); stride 12 fl
};

union SmemU {
    struct { float w_s[32 * 256]; float xs[2][64 * 32]; } g;   // 48KB
    RecurEx ex[8];                                              // 6KB
};

__global__ void __launch_bounds__(256)
qlstm_fused(const float* __restrict__ x,
            const float* __restrict__ Wf, const float* __restrict__ bf,
            const float* __restrict__ Wi, const float* __restrict__ bi,
            const float* __restrict__ Wu, const float* __restrict__ bu,
            const float* __restrict__ Wo, const float* __restrict__ bo,
            const float* __restrict__ pf, const float* __restrict__ pi_,
            const float* __restrict__ pu, const float* __restrict__ po,
            float* __restrict__ out)
{
    __shared__ __align__(16) SmemU sm;

    const int tid  = threadIdx.x;
    const int lane = tid & 31;

    if (blockIdx.x >= RECUR_BLOCKS) {
        // ================= GEMM role: 64 rows = tile gb ====================
        const int gb   = blockIdx.x - RECUR_BLOCKS;
        const int warp = tid >> 5;
        const int row0  = gb * 64;
        const int wrow0 = warp * 8;

        float* w_s = sm.g.w_s;

        #pragma unroll
        for (int i = 0; i < 8; i++) {
            int idx = tid + 256 * i;
            int o = idx >> 6, s = idx & 63;
            int sw = (s & ~7) | ((s & 7) ^ (o & 7));
            int g = o >> 3, q = o & 7;
            const float* base = (g == 0 ? Wf : (g == 1 ? Wi : (g == 2 ? Wu : Wo)));
            cpasync16(&w_s[o * 256 + sw * 4], base + q * DIN + s * 4);
        }

        auto load_x = [&](int kc, int buf) {
            #pragma unroll
            for (int i = 0; i < 2; i++) {
                int idx = tid + 256 * i;          // 512 slots: 64 rows x 8 slots
                int r = idx >> 3, s = idx & 7;
                cpasync16(&sm.g.xs[buf][r * 32 + s * 4],
                          x + (size_t)(row0 + r) * IN_DIM + kc * KCH + s * 4);
            }
        };

        load_x(0, 0); cp_commit();                // group: {W, x0}

        ull acc[8];
        #pragma unroll
        for (int r = 0; r < 8; r++) acc[r] = 0ULL;

        #pragma unroll 1
        for (int kc = 0; kc < NCHUNK; kc++) {
            if (kc < NCHUNK - 1) { load_x(kc + 1, (kc + 1) & 1); cp_commit(); }
            if (kc < NCHUNK - 1) cp_wait<1>(); else cp_wait<0>();
            __syncthreads();

            ull wreg[16];
            #pragma unroll
            for (int j = 0; j < 8; j++) {
                int s  = kc * 8 + j;
                int sw = (s & ~7) | ((s & 7) ^ (lane & 7));
                ulonglong2 wv = *reinterpret_cast<const ulonglong2*>(&w_s[lane * 256 + sw * 4]);
                wreg[2 * j] = wv.x; wreg[2 * j + 1] = wv.y;
            }

            const float* xb = sm.g.xs[kc & 1];
            #pragma unroll
            for (int r = 0; r < 8; r++) {
                const ulonglong2* xp = reinterpret_cast<const ulonglong2*>(xb + (wrow0 + r) * 32);
                #pragma unroll
                for (int j = 0; j < 8; j++) {
                    ulonglong2 xv = xp[j];         // full-warp broadcast LDS.128
                    ffma2(acc[r], xv.x, wreg[2 * j]);
                    ffma2(acc[r], xv.y, wreg[2 * j + 1]);
                }
            }
            __syncthreads();
        }

        const int g = lane >> 3, q = lane & 7;    // this lane's output o = g*8+q
        const float bias = (g == 0 ? bf : (g == 1 ? bi : (g == 2 ? bu : bo)))[q];

        #pragma unroll
        for (int r = 0; r < 8; r++) {
            float2 p = *reinterpret_cast<float2*>(&acc[r]);
            // gate-minor column: still 32 distinct cols per warp -> coalesced
            g_zx[(size_t)(row0 + wrow0 + r) * 32 + q * 4 + g] = p.x + p.y + bias;
        }

        __syncthreads();
        if (tid == 0) st_rel(&g_flag[gb], 1u);     // fidx == gb == t*8 + oct
    } else {
        // ========== RECUR role: lane = (elem, qubit), 4 elems/warp =========
        const int wid = tid >> 5;
        const int e   = lane >> 3, q = lane & 7;
        const int b   = blockIdx.x * 32 + wid * 4 + e;
        const int oct = blockIdx.x >> 1;           // uniform across block

        RecurEx& ex = sm.ex[wid];

        // recurrent weights for this qubit, packed (f,i) and (u,o)
        ull wfi[8], wuo[8];
        #pragma unroll
        for (int j = 0; j < 8; j++) {
            wfi[j] = pack2(Wf[q * DIN + IN_DIM + j], Wi[q * DIN + IN_DIM + j]);
            wuo[j] = pack2(Wu[q * DIN + IN_DIM + j], Wo[q * DIN + IN_DIM + j]);
        }
        float cthf = __cosf(pf[q]), cthi = __cosf(pi_[q]);
        float cthu = __cosf(pu[q]), ctho = __cosf(po[q]);
        if (q == 0) { cthf *= 0.5f; cthi *= 0.5f; ctho *= 0.5f; }  // sigmoid 0.5x fold

        const float* zp = g_zx + (size_t)b * 32 + q * 4;
        const size_t zstr = (size_t)BATCH * 32;

        float* hx_out = out + (size_t)SEQ * BATCH * HDIM;
        float* cx_out = hx_out + (size_t)BATCH * HDIM;

        ull h2[8];
        #pragma unroll
        for (int j = 0; j < 8; j++) h2[j] = 0ULL;
        float c = 0.f, hnew = 0.f;

        // Windowed flag protocol (flags for t = w8+1..w8+8, loaded 1 window early)
        unsigned fv[8];
        auto load_flags = [&](int w8) {
            #pragma unroll
            for (int i = 0; i < 8; i++)
                fv[i] = ld_rlx(&g_flag[(w8 + 1 + i) * 8 + oct]);
        };

        {   // t=0 tile (blocking acquire)
            unsigned r = ld_acq(&g_flag[oct]);
            while (r == 0) { __nanosleep(128); r = ld_acq(&g_flag[oct]); }
        }
        load_flags(0);
        ulonglong2 z2 = *reinterpret_cast<const ulonglong2*>(zp);

        #pragma unroll 1
        for (int w = 0; w < SEQ / 8; w++) {
            const int tw = w * 8;

            unsigned allv = fv[0] & fv[1] & fv[2] & fv[3] & fv[4] & fv[5] & fv[6] & fv[7];
            if (allv == 0) {
                #pragma unroll
                for (int i = 0; i < 8; i++) {
                    while (fv[i] == 0) {
                        __nanosleep(128);
                        fv[i] = ld_rlx(&g_flag[(tw + 1 + i) * 8 + oct]);
                    }
                }
            }
            fence_acq();
            if (w < SEQ / 8 - 1) load_flags(tw + 8);

            #pragma unroll
            for (int s = 0; s < 8; s++) {
                const int t = tw + s;
                ulonglong2 zn = *reinterpret_cast<const ulonglong2*>(
                    zp + (size_t)(t + 1) * zstr);

                // dot for all 4 gates: two parallel chains of 4 ffma2, then add
                ull zfiA = z2.x, zuoA = z2.y;
                #pragma unroll
                for (int j = 0; j < 4; j++) { ffma2(zfiA, h2[j], wfi[j]); ffma2(zuoA, h2[j], wuo[j]); }
                ull zfiB = mul2(h2[4], wfi[4]), zuoB = mul2(h2[4], wuo[4]);
                #pragma unroll
                for (int j = 5; j < 8; j++) { ffma2(zfiB, h2[j], wfi[j]); ffma2(zuoB, h2[j], wuo[j]); }
                float zfA, ziA, zuA, zoA, zfB, ziB, zuB, zoB;
                unpack2(zfA, ziA, zfiA); unpack2(zuA, zoA, zuoA);
                unpack2(zfB, ziB, zfiB); unpack2(zuB, zoB, zuoB);

                float cf = __cosf(zfA + zfB) * cthf;
                float ci = __cosf(ziA + ziB) * cthi;
                float cu = __cosf(zuA + zuB) * cthu;
                float co = __cosf(zoA + zoB) * ctho;

                // exchange 1: publish this qubit's 4 cos values (one STS.128)
                *reinterpret_cast<float4*>(&ex.cv[e][q * 4]) = make_float4(cf, ci, cu, co);
                __syncwarp();

                // masked packed prefix product over j <= q (7 mul2 per pair-tree)
                ull vfi[8], vuo[8];
                #pragma unroll
                for (int j = 0; j < 8; j++) {
                    ulonglong2 u = *reinterpret_cast<const ulonglong2*>(&ex.cv[e][j * 4]);
                    bool in = (j <= q);
                    vfi[j] = in ? u.x : ONE2;
                    vuo[j] = in ? u.y : ONE2;
                }
                ull pfi = mul2(mul2(mul2(vfi[0], vfi[1]), mul2(vfi[2], vfi[3])),
                               mul2(mul2(vfi[4], vfi[5]), mul2(vfi[6], vfi[7])));
                ull puo = mul2(mul2(mul2(vuo[0], vuo[1]), mul2(vuo[2], vuo[3])),
                               mul2(mul2(vuo[4], vuo[5]), mul2(vuo[6], vuo[7])));
                float Pf, Pi, Pu, Po;
                unpack2(Pf, Pi, pfi); unpack2(Pu, Po, puo);

                // activations (all local to the lane now)
                float af = fmaf(0.5f, tanh_approx(Pf), 0.5f);
                float ai = fmaf(0.5f, tanh_approx(Pi), 0.5f);
                float tu = tanh_approx(Pu);
                float ao = fmaf(0.5f, tanh_approx(Po), 0.5f);

                c    = fmaf(af, c, ai * tu);
                hnew = ao * tanh_approx(c);

                // exchange 2: broadcast h vector within the element group
                ex.h[e][q] = hnew;
                __syncwarp();
                float4 ha = *reinterpret_cast<const float4*>(&ex.h[e][0]);
                float4 hb = *reinterpret_cast<const float4*>(&ex.h[e][4]);
                h2[0] = pack2(ha.x, ha.x); h2[1] = pack2(ha.y, ha.y);
                h2[2] = pack2(ha.z, ha.z); h2[3] = pack2(ha.w, ha.w);
                h2[4] = pack2(hb.x, hb.x); h2[5] = pack2(hb.y, hb.y);
                h2[6] = pack2(hb.z, hb.z); h2[7] = pack2(hb.w, hb.w);

                // coalesced: 32 lanes -> 32 consecutive floats
                out[(size_t)t * (BATCH * HDIM) + (size_t)b * HDIM + q] = hnew;
                z2 = zn;
            }
        }

        hx_out[(size_t)b * HDIM + q] = hnew;
        cx_out[(size_t)b * HDIM + q] = c;
    }
}

extern "C" void kernel_launch(void* const* d_in, const int* in_sizes, int n_in,
                              void* d_out, int out_size) {
    const float* inputs = (const float*)d_in[0];
    const float* Wf = (const float*)d_in[1];  const float* bf = (const float*)d_in[2];
    const float* Wi = (const float*)d_in[3];  const float* bi = (const float*)d_in[4];
    const float* Wu = (const float*)d_in[5];  const float* bu = (const float*)d_in[6];
    const float* Wo = (const float*)d_in[7];  const float* bo = (const float*)d_in[8];
    const float* pf  = (const float*)d_in[9];
    const float* pi_ = (const float*)d_in[10];
    const float* pu  = (const float*)d_in[11];
    const float* po  = (const float*)d_in[12];
    float* out = (float*)d_out;

    init_flags<<<9, 256>>>();
    qlstm_fused<<<RECUR_BLOCKS + GEMM_BLOCKS, 256>>>(
        inputs, Wf, bf, Wi, bi, Wu, bu, Wo, bo, pf, pi_, pu, po, out);
}